// round 11
// baseline (speedup 1.0000x reference)
#include <cuda_runtime.h>
#include <cuda_bf16.h>
#include <math.h>
#include <stdint.h>

#define NLEV 16
#define P2 2654435761u
#define P3 805459861u

struct LevelParams {
    int          R[NLEV];
    unsigned int H[NLEV];
    int          O[NLEV];
    int          linear[NLEV];
};

// Prepared weight tile images (global scratch; staged to smem per CTA).
__device__ __align__(16) unsigned g_w1b[2048];
__device__ __align__(16) unsigned g_w2b[512];

// smem layout (static): A tile 256x128B, w1 tile 64x128B, w2 tile 16x128B
#define SMEM_A   0
#define SMEM_W1  32768
#define SMEM_W2  40960
#define SMEM_TOT 43008

#define SW128(o) ((o) ^ (((o) >> 3) & 0x70))

// ---------------- helpers ----------------
__device__ __forceinline__ uint32_t smem_to_u32(const void* p) {
    uint32_t a;
    asm("{ .reg .u64 t; cvta.to.shared.u64 t, %1; cvt.u32.u64 %0, t; }" : "=r"(a) : "l"(p));
    return a;
}
__device__ __forceinline__ unsigned long long pack2(float lo, float hi) {
    unsigned long long r;
    asm("mov.b64 %0, {%1, %2};" : "=l"(r) : "f"(lo), "f"(hi));
    return r;
}
__device__ __forceinline__ void unpack2(unsigned long long v, float &lo, float &hi) {
    asm("mov.b64 {%0, %1}, %2;" : "=f"(lo), "=f"(hi) : "l"(v));
}
__device__ __forceinline__ void ffma2(unsigned long long &d, unsigned long long a, unsigned long long b) {
    asm("fma.rn.f32x2 %0, %1, %2, %0;" : "+l"(d) : "l"(a), "l"(b));
}
__device__ __forceinline__ unsigned packbf(__nv_bfloat16 a, __nv_bfloat16 b) {
    __nv_bfloat162 t = __halves2bfloat162(a, b);   // lo16=a, hi16=b
    unsigned r; memcpy(&r, &t, 4); return r;
}
__device__ __forceinline__ unsigned cvt_pack_bf(float lo, float hi) {
    unsigned r;
    asm("cvt.rn.bf16x2.f32 %0, %1, %2;" : "=r"(r) : "f"(hi), "f"(lo));
    return r;
}
__device__ __forceinline__ float bflo_f(unsigned u) { return __uint_as_float(u << 16); }
__device__ __forceinline__ float bfhi_f(unsigned u) { return __uint_as_float(u & 0xffff0000u); }

__device__ __forceinline__ void ldsm_x4(unsigned& r0, unsigned& r1, unsigned& r2, unsigned& r3, uint32_t a) {
    asm volatile("ldmatrix.sync.aligned.m8n8.x4.shared.b16 {%0,%1,%2,%3}, [%4];"
        : "=r"(r0), "=r"(r1), "=r"(r2), "=r"(r3) : "r"(a));
}
__device__ __forceinline__ void ldsm_x2(unsigned& r0, unsigned& r1, uint32_t a) {
    asm volatile("ldmatrix.sync.aligned.m8n8.x2.shared.b16 {%0,%1}, [%2];"
        : "=r"(r0), "=r"(r1) : "r"(a));
}
__device__ __forceinline__ void mma_bf16(float* d, const unsigned* a, const unsigned* b) {
    asm volatile("mma.sync.aligned.m16n8k16.row.col.f32.bf16.bf16.f32 "
        "{%0,%1,%2,%3}, {%4,%5,%6,%7}, {%8,%9}, {%0,%1,%2,%3};"
        : "+f"(d[0]), "+f"(d[1]), "+f"(d[2]), "+f"(d[3])
        : "r"(a[0]), "r"(a[1]), "r"(a[2]), "r"(a[3]), "r"(b[0]), "r"(b[1]));
}

// ---------------- merged prep kernel ----------------
__global__ void prep_weights_kernel(const float* __restrict__ w1,
                                    const float* __restrict__ w2) {
    int i = blockIdx.x * 256 + threadIdx.x;
    if (i < 2048) {
        int j = i >> 5, m = i & 31;
        int k = (m & 15) * 2;
        float v0 = w1[k * 64 + j];              // w1 is [32,64] row-major
        float v1 = w1[(k + 1) * 64 + j];
        __nv_bfloat16 h0 = __float2bfloat16(v0), h1 = __float2bfloat16(v1);
        unsigned r;
        if (m < 16) r = packbf(h0, h1);
        else r = packbf(__float2bfloat16(v0 - __bfloat162float(h0)),
                        __float2bfloat16(v1 - __bfloat162float(h1)));
        g_w1b[j * 32 + m] = r;
    } else if (i < 2560) {
        int k2 = i - 2048;
        int row = k2 >> 5, m = k2 & 31;
        int ok = row & 7, term = row >> 3;
        float v0 = w2[(2 * m) * 8 + ok];        // w2 is [64,8] row-major
        float v1 = w2[(2 * m + 1) * 8 + ok];
        __nv_bfloat16 h0 = __float2bfloat16(v0), h1 = __float2bfloat16(v1);
        unsigned r;
        if (!term) r = packbf(h0, h1);
        else r = packbf(__float2bfloat16(v0 - __bfloat162float(h0)),
                        __float2bfloat16(v1 - __bfloat162float(h1)));
        g_w2b[row * 32 + m] = r;
    }
}

// ---------------- encode helpers (proven) ----------------
__device__ __forceinline__ void setup_item(
    const float* __restrict__ xyz, float b, float inv2b, int p, int oc,
    float& ex, float& ey, float& ez, float& wt)
{
    float cx = (xyz[3 * p + 0] + b) * inv2b * 512.0f;
    float cy = (xyz[3 * p + 1] + b) * inv2b * 512.0f;
    float cz = (xyz[3 * p + 2] + b) * inv2b * 512.0f;
    int c0x = min(max((int)floorf(cx), 0), 511);
    int c0y = min(max((int)floorf(cy), 0), 511);
    int c0z = min(max((int)floorf(cz), 0), 511);
    float u = cx - (float)c0x, v = cy - (float)c0y, w = cz - (float)c0z;
    int ox = (oc >> 2) & 1, oy = (oc >> 1) & 1, oz = oc & 1;
    wt = (ox ? u : 1.0f - u) * (oy ? v : 1.0f - v) * (oz ? w : 1.0f - w);
    ex = (float)(c0x + ox) * (1.0f / 512.0f);
    ey = (float)(c0y + oy) * (1.0f / 512.0f);
    ez = (float)(c0z + oz) * (1.0f / 512.0f);
}
struct LevWts {
    float wx0, fx;
    float wyz00, wyz01, wyz10, wyz11;
    int ix, iy, iz;
};
__device__ __forceinline__ LevWts level_setup(float Rf, float ex, float ey, float ez) {
    LevWts s;
    float px = ex * Rf + 0.5f, py = ey * Rf + 0.5f, pz = ez * Rf + 0.5f;
    float pgx = floorf(px), pgy = floorf(py), pgz = floorf(pz);
    float fx = px - pgx, fy = py - pgy, fz = pz - pgz;
    s.ix = (int)pgx; s.iy = (int)pgy; s.iz = (int)pgz;
    s.fx = fx; s.wx0 = 1.0f - fx;
    float wy0 = 1.0f - fy, wz0 = 1.0f - fz;
    s.wyz00 = wy0 * wz0; s.wyz01 = wy0 * fz; s.wyz10 = fy * wz0; s.wyz11 = fy * fz;
    return s;
}
// split one level's packed feature to bf16 hi/lo
__device__ __forceinline__ void split_feat(unsigned long long a, unsigned& hi, unsigned& lo) {
    float f0, f1; unpack2(a, f0, f1);
    __nv_bfloat16 h0 = __float2bfloat16(f0);
    __nv_bfloat16 h1 = __float2bfloat16(f1);
    hi = packbf(h0, h1);
    lo = packbf(__float2bfloat16(f0 - __bfloat162float(h0)),
                __float2bfloat16(f1 - __bfloat162float(h1)));
}

// L1 prefetch of one encode-point's 8 gathers for level l (cheap-wavefront levels only).
__device__ __forceinline__ void prefetch_level(
    const LevelParams& lev, int l, const float* __restrict__ table,
    float ex, float ey, float ez)
{
    const float Rf = (float)lev.R[l];
    const unsigned H = lev.H[l];
    const unsigned long long* tab8 =
        reinterpret_cast<const unsigned long long*>(table) + lev.O[l];
    float px = ex * Rf + 0.5f, py = ey * Rf + 0.5f, pz = ez * Rf + 0.5f;
    int ix = (int)floorf(px), iy = (int)floorf(py), iz = (int)floorf(pz);
    if (lev.linear[l]) {
        int s1 = lev.R[l] + 1, s2 = s1 * s1;
        int base = ix + iy * s1 + iz * s2;
        #pragma unroll
        for (int dx = 0; dx < 2; dx++)
            #pragma unroll
            for (int dy = 0; dy < 2; dy++)
                #pragma unroll
                for (int dz = 0; dz < 2; dz++) {
                    int idx = base + dx + dy * s1 + dz * s2;
                    if (idx >= (int)H) idx -= (int)H;
                    asm volatile("prefetch.global.L1 [%0];" :: "l"(tab8 + idx));
                }
    } else {
        unsigned mask = H - 1u;
        unsigned hx0 = (unsigned)ix, hy0 = (unsigned)iy * P2, hz0 = (unsigned)iz * P3;
        #pragma unroll
        for (int dx = 0; dx < 2; dx++)
            #pragma unroll
            for (int dy = 0; dy < 2; dy++)
                #pragma unroll
                for (int dz = 0; dz < 2; dz++) {
                    unsigned idx = ((hx0 + (unsigned)dx)
                                  ^ (hy0 + (unsigned)dy * P2)
                                  ^ (hz0 + (unsigned)dz * P3)) & mask;
                    asm volatile("prefetch.global.L1 [%0];" :: "l"(tab8 + idx));
                }
    }
}

// ---------------- main kernel (R10 config + linear-level prefetch) ----------------
__global__ void __launch_bounds__(128, 4) grid_fused_kernel(
    const float* __restrict__ xyz,
    const float* __restrict__ bound,
    const float* __restrict__ table,
    float* __restrict__ out,
    LevelParams lev, int N)
{
    __shared__ __align__(1024) char smem[SMEM_TOT];
    const uint32_t sb = smem_to_u32(smem);
    const int tid = threadIdx.x;
    const int wid = tid >> 5;
    const int ln  = tid & 31;

    // stage weight tiles (swizzled)
    for (int i = tid; i < 2048; i += 128) {
        int row = i >> 5, m = i & 31;
        *reinterpret_cast<unsigned*>(smem + SMEM_W1 + SW128(row * 128 + m * 4)) = g_w1b[i];
    }
    for (int i = tid; i < 512; i += 128) {
        int row = i >> 5, m = i & 31;
        *reinterpret_cast<unsigned*>(smem + SMEM_W2 + SW128(row * 128 + m * 4)) = g_w2b[i];
    }
    __syncthreads();

    const int half = (N * 8) >> 1;
    int T = blockIdx.x * 128 + tid;          // exact fit: N*8/2 == 8192*128
    int gtA = T, gtB = T + half;
    int pA = gtA >> 3, pB = gtB >> 3;
    int oc = gtA & 7;

    const float b     = bound[0];
    const float inv2b = 1.0f / (2.0f * b);

    float exA, eyA, ezA, wtA, exB, eyB, ezB, wtB;
    setup_item(xyz, b, inv2b, pA, oc, exA, eyA, ezA, wtA);
    setup_item(xyz, b, inv2b, pB, oc, exB, eyB, ezB, wtB);

    const int rowA = wid * 64 + ln;
    const int rowB = rowA + 32;

    // warm the pipeline: prefetch levels 0 and 1 for both items
    prefetch_level(lev, 0, table, exA, eyA, ezA);
    prefetch_level(lev, 0, table, exB, eyB, ezB);
    prefetch_level(lev, 1, table, exA, eyA, ezA);
    prefetch_level(lev, 1, table, exB, eyB, ezB);

    // rolling 4-level hi/lo buffers (flushed via STS.128; same A-tile layout as R8)
    unsigned hiA[4], loA[4], hiB[4], loB[4];

    #pragma unroll
    for (int l = 0; l < NLEV; l++) {
        // distance-2 prefetch for the cheap-wavefront levels (covers levels 2..8:
        // linear 2-6 plus coarse hashed 7-8). Fine hashed levels 9-15 are NOT
        // prefetched: their duplicate wavefronts would saturate l1tex.
        if (l <= 6) {
            prefetch_level(lev, l + 2, table, exA, eyA, ezA);
            prefetch_level(lev, l + 2, table, exB, eyB, ezB);
        }

        const float Rf = (float)lev.R[l];
        const unsigned H = lev.H[l];
        const unsigned long long* tab8 =
            reinterpret_cast<const unsigned long long*>(table) + lev.O[l];
        LevWts A = level_setup(Rf, exA, eyA, ezA);
        LevWts B = level_setup(Rf, exB, eyB, ezB);
        unsigned long long aA = 0ull, aB = 0ull;
        if (lev.linear[l]) {
            int s1 = lev.R[l] + 1, s2 = s1 * s1;
            int baseA = A.ix + A.iy * s1 + A.iz * s2;
            int baseB = B.ix + B.iy * s1 + B.iz * s2;
            #pragma unroll
            for (int dx = 0; dx < 2; dx++) {
                float wxdA = dx ? A.fx : A.wx0;
                float wxdB = dx ? B.fx : B.wx0;
                #pragma unroll
                for (int dy = 0; dy < 2; dy++) {
                    #pragma unroll
                    for (int dz = 0; dz < 2; dz++) {
                        int idxA = baseA + dx + dy * s1 + dz * s2;
                        int idxB = baseB + dx + dy * s1 + dz * s2;
                        if (idxA >= (int)H) idxA -= (int)H;
                        if (idxB >= (int)H) idxB -= (int)H;
                        unsigned long long tA = __ldg(tab8 + idxA);
                        unsigned long long tB = __ldg(tab8 + idxB);
                        float wA = wxdA * (dy ? (dz ? A.wyz11 : A.wyz10)
                                              : (dz ? A.wyz01 : A.wyz00));
                        float wB = wxdB * (dy ? (dz ? B.wyz11 : B.wyz10)
                                              : (dz ? B.wyz01 : B.wyz00));
                        ffma2(aA, pack2(wA, wA), tA);
                        ffma2(aB, pack2(wB, wB), tB);
                    }
                }
            }
        } else {
            unsigned mask = H - 1u;
            unsigned hxA0 = (unsigned)A.ix,      hxA1 = hxA0 + 1u;
            unsigned hyA0 = (unsigned)A.iy * P2, hyA1 = hyA0 + P2;
            unsigned hzA0 = (unsigned)A.iz * P3, hzA1 = hzA0 + P3;
            unsigned hxB0 = (unsigned)B.ix,      hxB1 = hxB0 + 1u;
            unsigned hyB0 = (unsigned)B.iy * P2, hyB1 = hyB0 + P2;
            unsigned hzB0 = (unsigned)B.iz * P3, hzB1 = hzB0 + P3;
            #pragma unroll
            for (int dx = 0; dx < 2; dx++) {
                float wxdA = dx ? A.fx : A.wx0;
                float wxdB = dx ? B.fx : B.wx0;
                unsigned hxA = dx ? hxA1 : hxA0;
                unsigned hxB = dx ? hxB1 : hxB0;
                #pragma unroll
                for (int dy = 0; dy < 2; dy++) {
                    unsigned hxyA = hxA ^ (dy ? hyA1 : hyA0);
                    unsigned hxyB = hxB ^ (dy ? hyB1 : hyB0);
                    #pragma unroll
                    for (int dz = 0; dz < 2; dz++) {
                        unsigned idxA = (hxyA ^ (dz ? hzA1 : hzA0)) & mask;
                        unsigned idxB = (hxyB ^ (dz ? hzB1 : hzB0)) & mask;
                        unsigned long long tA = __ldg(tab8 + idxA);
                        unsigned long long tB = __ldg(tab8 + idxB);
                        float wA = wxdA * (dy ? (dz ? A.wyz11 : A.wyz10)
                                              : (dz ? A.wyz01 : A.wyz00));
                        float wB = wxdB * (dy ? (dz ? B.wyz11 : B.wyz10)
                                              : (dz ? B.wyz01 : B.wyz00));
                        ffma2(aA, pack2(wA, wA), tA);
                        ffma2(aB, pack2(wB, wB), tB);
                    }
                }
            }
        }
        split_feat(aA, hiA[l & 3], loA[l & 3]);
        split_feat(aB, hiB[l & 3], loB[l & 3]);
        if ((l & 3) == 3) {
            int q = l >> 2;
            *reinterpret_cast<uint4*>(smem + SMEM_A + SW128(rowA * 128 + q * 16)) =
                make_uint4(hiA[0], hiA[1], hiA[2], hiA[3]);
            *reinterpret_cast<uint4*>(smem + SMEM_A + SW128(rowA * 128 + 64 + q * 16)) =
                make_uint4(loA[0], loA[1], loA[2], loA[3]);
            *reinterpret_cast<uint4*>(smem + SMEM_A + SW128(rowB * 128 + q * 16)) =
                make_uint4(hiB[0], hiB[1], hiB[2], hiB[3]);
            *reinterpret_cast<uint4*>(smem + SMEM_A + SW128(rowB * 128 + 64 + q * 16)) =
                make_uint4(loB[0], loB[1], loB[2], loB[3]);
        }
    }
    __syncwarp();

    // ---- w1 B-fragments loaded once (R8-proven): b1[nt][term][kst][reg] ----
    unsigned b1[8][2][2][2];
    #pragma unroll
    for (int nt = 0; nt < 8; nt++) {
        #pragma unroll
        for (int term = 0; term < 2; term++) {
            uint32_t row  = nt * 8 + (ln & 7);
            uint32_t byte = term * 64 + (ln >> 3) * 16;
            uint32_t ad = sb + SMEM_W1 + SW128(row * 128 + byte);
            ldsm_x4(b1[nt][term][0][0], b1[nt][term][0][1],
                    b1[nt][term][1][0], b1[nt][term][1][1], ad);
        }
    }

    const int baseAI = blockIdx.x * 128 + wid * 32;   // global item idx of warp row 0

    #pragma unroll
    for (int t = 0; t < 4; t++) {
        // A1 fragments for this mtile (hi/lo x 2 ksteps)
        unsigned ahi[2][4], alo[2][4];
        #pragma unroll
        for (int s = 0; s < 2; s++) {
            int mat = ln >> 3;
            uint32_t row  = wid * 64 + t * 16 + (mat & 1) * 8 + (ln & 7);
            uint32_t byteh = s * 32 + (mat >> 1) * 16;
            ldsm_x4(ahi[s][0], ahi[s][1], ahi[s][2], ahi[s][3],
                    sb + SMEM_A + SW128(row * 128 + byteh));
            ldsm_x4(alo[s][0], alo[s][1], alo[s][2], alo[s][3],
                    sb + SMEM_A + SW128(row * 128 + 64 + byteh));
        }
        float wsrc = (t < 2) ? wtA : wtB;
        int tq = (t & 1) * 16;
        float wt0 = __shfl_sync(0xffffffffu, wsrc, tq + (ln >> 2));
        float wt1 = __shfl_sync(0xffffffffu, wsrc, tq + 8 + (ln >> 2));

        float D2[4] = {0.f, 0.f, 0.f, 0.f};
        #pragma unroll
        for (int s2 = 0; s2 < 4; s2++) {     // gemm2 kstep == gemm1 ntile pair
            unsigned a2hi[4], a2lo[4];
            #pragma unroll
            for (int e = 0; e < 2; e++) {
                int nt = 2 * s2 + e;
                float D1[4] = {0.f, 0.f, 0.f, 0.f};
                mma_bf16(D1, ahi[0], b1[nt][0][0]);   // hi*hi
                mma_bf16(D1, ahi[1], b1[nt][0][1]);
                mma_bf16(D1, ahi[0], b1[nt][1][0]);   // hi*lo
                mma_bf16(D1, ahi[1], b1[nt][1][1]);
                mma_bf16(D1, alo[0], b1[nt][0][0]);   // lo*hi
                mma_bf16(D1, alo[1], b1[nt][0][1]);
                float h0 = fmaxf(D1[0], 0.f) * wt0;
                float h1 = fmaxf(D1[1], 0.f) * wt0;
                float h2 = fmaxf(D1[2], 0.f) * wt1;
                float h3 = fmaxf(D1[3], 0.f) * wt1;
                unsigned p01 = cvt_pack_bf(h0, h1);
                unsigned p23 = cvt_pack_bf(h2, h3);
                a2hi[2 * e + 0] = p01;
                a2hi[2 * e + 1] = p23;
                a2lo[2 * e + 0] = cvt_pack_bf(h0 - bflo_f(p01), h1 - bfhi_f(p01));
                a2lo[2 * e + 1] = cvt_pack_bf(h2 - bflo_f(p23), h3 - bfhi_f(p23));
            }
            // w2 B-fragments for this kstep
            unsigned b2h[2], b2l[2];
            {
                int mat = (ln >> 3) & 1;
                uint32_t byte = s2 * 32 + mat * 16;
                ldsm_x2(b2h[0], b2h[1], sb + SMEM_W2 + SW128((ln & 7) * 128 + byte));
                ldsm_x2(b2l[0], b2l[1], sb + SMEM_W2 + SW128((8 + (ln & 7)) * 128 + byte));
            }
            mma_bf16(D2, a2hi, b2h);
            mma_bf16(D2, a2hi, b2l);
            mma_bf16(D2, a2lo, b2h);
        }

        // reduce the 8 corner-rows (quads hold distinct rows; cols preserved)
        #pragma unroll
        for (int k = 0; k < 4; k++) {
            D2[k] += __shfl_xor_sync(0xffffffffu, D2[k], 4);
            D2[k] += __shfl_xor_sync(0xffffffffu, D2[k], 8);
            D2[k] += __shfl_xor_sync(0xffffffffu, D2[k], 16);
        }
        int obase = (t < 2) ? (baseAI + 16 * t) : (baseAI + half + 16 * (t - 2));
        if (ln < 4) {
            *reinterpret_cast<float2*>(out + obase + 2 * ln) = make_float2(D2[0], D2[1]);
        } else if (ln < 8) {
            *reinterpret_cast<float2*>(out + obase + 8 + 2 * (ln - 4)) = make_float2(D2[2], D2[3]);
        }
    }
}

extern "C" void kernel_launch(void* const* d_in, const int* in_sizes, int n_in,
                              void* d_out, int out_size)
{
    const float* xyz   = (const float*)d_in[0];
    const float* bound = (const float*)d_in[1];
    const float* table = (const float*)d_in[2];
    const float* w1    = (const float*)d_in[3];
    const float* w2    = (const float*)d_in[4];
    float* out = (float*)d_out;

    int N = in_sizes[0] / 3;

    prep_weights_kernel<<<10, 256>>>(w1, w2);

    // torch-ngp level construction (exact numpy double math)
    LevelParams lev;
    double scale = exp2(log2(513.0 / 16.0) / 15.0);
    long long off = 0;
    for (int i = 0; i < NLEV; i++) {
        int res = (int)ceil(16.0 * pow(scale, (double)i));
        long long cube = (long long)(res + 1) * (res + 1) * (res + 1);
        long long n = cube;
        if (n > (1LL << 19)) n = (1LL << 19);
        n = ((n + 7) / 8) * 8;
        lev.R[i] = res;
        lev.H[i] = (unsigned)n;
        lev.O[i] = (int)off;
        lev.linear[i] = (cube <= n) ? 1 : 0;
        off += n;
    }

    int half = (N * 8) / 2;
    int blocks = (half + 127) / 128;
    grid_fused_kernel<<<blocks, 128>>>(xyz, bound, table, out, lev, N);
}

// round 12
// speedup vs baseline: 1.4305x; 1.4305x over previous
#include <cuda_runtime.h>
#include <cuda_bf16.h>
#include <math.h>
#include <stdint.h>

#define NLEV 16
#define P2 2654435761u
#define P3 805459861u

struct LevelParams {
    int          R[NLEV];
    unsigned int H[NLEV];
    int          O[NLEV];
    int          linear[NLEV];
};

// Weights pre-arranged in mma FRAGMENT order by the prep kernel:
// g_f1[q*32 + ln] = w1 B-fragment word for lane ln, q = nt*8 + term*4 + s*2 + r
// g_f2[q*32 + ln] = w2 B-fragment word for lane ln, q = s2*4 + term*2 + r
__device__ __align__(16) unsigned g_f1[2048];
__device__ __align__(16) unsigned g_f2[512];

// smem: A tile only, 256 rows x 128B (warp-private quarters)
#define SMEM_TOT 32768
#define SW128(o) ((o) ^ (((o) >> 3) & 0x70))

// ---------------- helpers ----------------
__device__ __forceinline__ uint32_t smem_to_u32(const void* p) {
    uint32_t a;
    asm("{ .reg .u64 t; cvta.to.shared.u64 t, %1; cvt.u32.u64 %0, t; }" : "=r"(a) : "l"(p));
    return a;
}
__device__ __forceinline__ unsigned long long pack2(float lo, float hi) {
    unsigned long long r;
    asm("mov.b64 %0, {%1, %2};" : "=l"(r) : "f"(lo), "f"(hi));
    return r;
}
__device__ __forceinline__ void unpack2(unsigned long long v, float &lo, float &hi) {
    asm("mov.b64 {%0, %1}, %2;" : "=f"(lo), "=f"(hi) : "l"(v));
}
__device__ __forceinline__ void ffma2(unsigned long long &d, unsigned long long a, unsigned long long b) {
    asm("fma.rn.f32x2 %0, %1, %2, %0;" : "+l"(d) : "l"(a), "l"(b));
}
__device__ __forceinline__ unsigned packbf(__nv_bfloat16 a, __nv_bfloat16 b) {
    __nv_bfloat162 t = __halves2bfloat162(a, b);   // lo16=a, hi16=b
    unsigned r; memcpy(&r, &t, 4); return r;
}
__device__ __forceinline__ unsigned cvt_pack_bf(float lo, float hi) {
    unsigned r;
    asm("cvt.rn.bf16x2.f32 %0, %1, %2;" : "=r"(r) : "f"(hi), "f"(lo));
    return r;
}
__device__ __forceinline__ float bflo_f(unsigned u) { return __uint_as_float(u << 16); }
__device__ __forceinline__ float bfhi_f(unsigned u) { return __uint_as_float(u & 0xffff0000u); }

__device__ __forceinline__ void ldsm_x4(unsigned& r0, unsigned& r1, unsigned& r2, unsigned& r3, uint32_t a) {
    asm volatile("ldmatrix.sync.aligned.m8n8.x4.shared.b16 {%0,%1,%2,%3}, [%4];"
        : "=r"(r0), "=r"(r1), "=r"(r2), "=r"(r3) : "r"(a));
}
__device__ __forceinline__ void mma_bf16(float* d, const unsigned* a, const unsigned* b) {
    asm volatile("mma.sync.aligned.m16n8k16.row.col.f32.bf16.bf16.f32 "
        "{%0,%1,%2,%3}, {%4,%5,%6,%7}, {%8,%9}, {%0,%1,%2,%3};"
        : "+f"(d[0]), "+f"(d[1]), "+f"(d[2]), "+f"(d[3])
        : "r"(a[0]), "r"(a[1]), "r"(a[2]), "r"(a[3]), "r"(b[0]), "r"(b[1]));
}

// ---------------- prep kernel: emit weights in fragment order ----------------
// Fragment mapping (validated by R8/R10 passing): for mma.m16n8k16.row.col,
// B-fragment reg r of kstep s holds pairs B[k0..k0+1][n] with
// k0 = 16*s + 8*r + (ln&3)*2, n = ln>>2 (plus tile offsets).
__global__ void prep_weights_kernel(const float* __restrict__ w1,
                                    const float* __restrict__ w2) {
    int i = blockIdx.x * 256 + threadIdx.x;
    if (i < 2048) {
        int q = i >> 5, ln = i & 31;
        int nt = q >> 3, term = (q >> 2) & 1, s = (q >> 1) & 1, r = q & 1;
        int j  = nt * 8 + (ln >> 2);            // hidden unit (n within tile nt)
        int k0 = 16 * s + 8 * r + (ln & 3) * 2; // input feature index
        float v0 = w1[k0 * 64 + j];             // w1 is [32,64] row-major
        float v1 = w1[(k0 + 1) * 64 + j];
        __nv_bfloat16 h0 = __float2bfloat16(v0), h1 = __float2bfloat16(v1);
        unsigned rr;
        if (!term) rr = packbf(h0, h1);
        else rr = packbf(__float2bfloat16(v0 - __bfloat162float(h0)),
                         __float2bfloat16(v1 - __bfloat162float(h1)));
        g_f1[i] = rr;
    } else if (i < 2560) {
        int k2 = i - 2048;
        int q = k2 >> 5, ln = k2 & 31;
        int s2 = q >> 2, term = (q >> 1) & 1, r = q & 1;
        int n  = ln >> 2;                        // output index 0..7
        int k0 = 16 * s2 + 8 * r + (ln & 3) * 2; // hidden index 0..63
        float v0 = w2[k0 * 8 + n];               // w2 is [64,8] row-major
        float v1 = w2[(k0 + 1) * 8 + n];
        __nv_bfloat16 h0 = __float2bfloat16(v0), h1 = __float2bfloat16(v1);
        unsigned rr;
        if (!term) rr = packbf(h0, h1);
        else rr = packbf(__float2bfloat16(v0 - __bfloat162float(h0)),
                         __float2bfloat16(v1 - __bfloat162float(h1)));
        g_f2[k2] = rr;
    }
}

// ---------------- encode helpers (proven) ----------------
__device__ __forceinline__ void setup_item(
    const float* __restrict__ xyz, float b, float inv2b, int p, int oc,
    float& ex, float& ey, float& ez, float& wt)
{
    float cx = (xyz[3 * p + 0] + b) * inv2b * 512.0f;
    float cy = (xyz[3 * p + 1] + b) * inv2b * 512.0f;
    float cz = (xyz[3 * p + 2] + b) * inv2b * 512.0f;
    int c0x = min(max((int)floorf(cx), 0), 511);
    int c0y = min(max((int)floorf(cy), 0), 511);
    int c0z = min(max((int)floorf(cz), 0), 511);
    float u = cx - (float)c0x, v = cy - (float)c0y, w = cz - (float)c0z;
    int ox = (oc >> 2) & 1, oy = (oc >> 1) & 1, oz = oc & 1;
    wt = (ox ? u : 1.0f - u) * (oy ? v : 1.0f - v) * (oz ? w : 1.0f - w);
    ex = (float)(c0x + ox) * (1.0f / 512.0f);
    ey = (float)(c0y + oy) * (1.0f / 512.0f);
    ez = (float)(c0z + oz) * (1.0f / 512.0f);
}
struct LevWts {
    float wx0, fx;
    float wyz00, wyz01, wyz10, wyz11;
    int ix, iy, iz;
};
__device__ __forceinline__ LevWts level_setup(float Rf, float ex, float ey, float ez) {
    LevWts s;
    float px = ex * Rf + 0.5f, py = ey * Rf + 0.5f, pz = ez * Rf + 0.5f;
    float pgx = floorf(px), pgy = floorf(py), pgz = floorf(pz);
    float fx = px - pgx, fy = py - pgy, fz = pz - pgz;
    s.ix = (int)pgx; s.iy = (int)pgy; s.iz = (int)pgz;
    s.fx = fx; s.wx0 = 1.0f - fx;
    float wy0 = 1.0f - fy, wz0 = 1.0f - fz;
    s.wyz00 = wy0 * wz0; s.wyz01 = wy0 * fz; s.wyz10 = fy * wz0; s.wyz11 = fy * fz;
    return s;
}
// split one level's packed feature to bf16 hi/lo
__device__ __forceinline__ void split_feat(unsigned long long a, unsigned& hi, unsigned& lo) {
    float f0, f1; unpack2(a, f0, f1);
    __nv_bfloat16 h0 = __float2bfloat16(f0);
    __nv_bfloat16 h1 = __float2bfloat16(f1);
    hi = packbf(h0, h1);
    lo = packbf(__float2bfloat16(f0 - __bfloat162float(h0)),
                __float2bfloat16(f1 - __bfloat162float(h1)));
}

// ---------------- main kernel (R10 structure, fragment-direct weights) ----------------
__global__ void __launch_bounds__(128, 4) grid_fused_kernel(
    const float* __restrict__ xyz,
    const float* __restrict__ bound,
    const float* __restrict__ table,
    float* __restrict__ out,
    LevelParams lev, int N)
{
    __shared__ __align__(1024) char smem[SMEM_TOT];   // A tile only (warp-private quarters)
    const uint32_t sb = smem_to_u32(smem);
    const int tid = threadIdx.x;
    const int wid = tid >> 5;
    const int ln  = tid & 31;

    const int half = (N * 8) >> 1;
    int T = blockIdx.x * 128 + tid;          // exact fit: N*8/2 == 8192*128
    int gtA = T, gtB = T + half;
    int pA = gtA >> 3, pB = gtB >> 3;
    int oc = gtA & 7;

    const float b     = bound[0];
    const float inv2b = 1.0f / (2.0f * b);

    float exA, eyA, ezA, wtA, exB, eyB, ezB, wtB;
    setup_item(xyz, b, inv2b, pA, oc, exA, eyA, ezA, wtA);
    setup_item(xyz, b, inv2b, pB, oc, exB, eyB, ezB, wtB);

    const int rowA = wid * 64 + ln;
    const int rowB = rowA + 32;

    // rolling 4-level hi/lo buffers (flushed via STS.128; same A-tile layout as R8)
    unsigned hiA[4], loA[4], hiB[4], loB[4];

    #pragma unroll
    for (int l = 0; l < NLEV; l++) {
        const float Rf = (float)lev.R[l];
        const unsigned H = lev.H[l];
        const unsigned long long* tab8 =
            reinterpret_cast<const unsigned long long*>(table) + lev.O[l];
        LevWts A = level_setup(Rf, exA, eyA, ezA);
        LevWts B = level_setup(Rf, exB, eyB, ezB);
        unsigned long long aA = 0ull, aB = 0ull;
        if (lev.linear[l]) {
            int s1 = lev.R[l] + 1, s2 = s1 * s1;
            int baseA = A.ix + A.iy * s1 + A.iz * s2;
            int baseB = B.ix + B.iy * s1 + B.iz * s2;
            #pragma unroll
            for (int dx = 0; dx < 2; dx++) {
                float wxdA = dx ? A.fx : A.wx0;
                float wxdB = dx ? B.fx : B.wx0;
                #pragma unroll
                for (int dy = 0; dy < 2; dy++) {
                    #pragma unroll
                    for (int dz = 0; dz < 2; dz++) {
                        int idxA = baseA + dx + dy * s1 + dz * s2;
                        int idxB = baseB + dx + dy * s1 + dz * s2;
                        if (idxA >= (int)H) idxA -= (int)H;
                        if (idxB >= (int)H) idxB -= (int)H;
                        unsigned long long tA = __ldg(tab8 + idxA);
                        unsigned long long tB = __ldg(tab8 + idxB);
                        float wA = wxdA * (dy ? (dz ? A.wyz11 : A.wyz10)
                                              : (dz ? A.wyz01 : A.wyz00));
                        float wB = wxdB * (dy ? (dz ? B.wyz11 : B.wyz10)
                                              : (dz ? B.wyz01 : B.wyz00));
                        ffma2(aA, pack2(wA, wA), tA);
                        ffma2(aB, pack2(wB, wB), tB);
                    }
                }
            }
        } else {
            unsigned mask = H - 1u;
            unsigned hxA0 = (unsigned)A.ix,      hxA1 = hxA0 + 1u;
            unsigned hyA0 = (unsigned)A.iy * P2, hyA1 = hyA0 + P2;
            unsigned hzA0 = (unsigned)A.iz * P3, hzA1 = hzA0 + P3;
            unsigned hxB0 = (unsigned)B.ix,      hxB1 = hxB0 + 1u;
            unsigned hyB0 = (unsigned)B.iy * P2, hyB1 = hyB0 + P2;
            unsigned hzB0 = (unsigned)B.iz * P3, hzB1 = hzB0 + P3;
            #pragma unroll
            for (int dx = 0; dx < 2; dx++) {
                float wxdA = dx ? A.fx : A.wx0;
                float wxdB = dx ? B.fx : B.wx0;
                unsigned hxA = dx ? hxA1 : hxA0;
                unsigned hxB = dx ? hxB1 : hxB0;
                #pragma unroll
                for (int dy = 0; dy < 2; dy++) {
                    unsigned hxyA = hxA ^ (dy ? hyA1 : hyA0);
                    unsigned hxyB = hxB ^ (dy ? hyB1 : hyB0);
                    #pragma unroll
                    for (int dz = 0; dz < 2; dz++) {
                        unsigned idxA = (hxyA ^ (dz ? hzA1 : hzA0)) & mask;
                        unsigned idxB = (hxyB ^ (dz ? hzB1 : hzB0)) & mask;
                        unsigned long long tA = __ldg(tab8 + idxA);
                        unsigned long long tB = __ldg(tab8 + idxB);
                        float wA = wxdA * (dy ? (dz ? A.wyz11 : A.wyz10)
                                              : (dz ? A.wyz01 : A.wyz00));
                        float wB = wxdB * (dy ? (dz ? B.wyz11 : B.wyz10)
                                              : (dz ? B.wyz01 : B.wyz00));
                        ffma2(aA, pack2(wA, wA), tA);
                        ffma2(aB, pack2(wB, wB), tB);
                    }
                }
            }
        }
        split_feat(aA, hiA[l & 3], loA[l & 3]);
        split_feat(aB, hiB[l & 3], loB[l & 3]);
        if ((l & 3) == 3) {
            int q = l >> 2;
            *reinterpret_cast<uint4*>(smem + SW128(rowA * 128 + q * 16)) =
                make_uint4(hiA[0], hiA[1], hiA[2], hiA[3]);
            *reinterpret_cast<uint4*>(smem + SW128(rowA * 128 + 64 + q * 16)) =
                make_uint4(loA[0], loA[1], loA[2], loA[3]);
            *reinterpret_cast<uint4*>(smem + SW128(rowB * 128 + q * 16)) =
                make_uint4(hiB[0], hiB[1], hiB[2], hiB[3]);
            *reinterpret_cast<uint4*>(smem + SW128(rowB * 128 + 64 + q * 16)) =
                make_uint4(loB[0], loB[1], loB[2], loB[3]);
        }
    }
    __syncwarp();

    // ---- w1 fragments: direct from global in fragment order (broadcast-cached) ----
    unsigned b1f[64];
    #pragma unroll
    for (int q = 0; q < 64; q++) b1f[q] = __ldg(&g_f1[q * 32 + ln]);

    const int baseAI = blockIdx.x * 128 + wid * 32;   // global item idx of warp row 0

    #pragma unroll
    for (int t = 0; t < 4; t++) {
        // A1 fragments for this mtile (hi/lo x 2 ksteps)
        unsigned ahi[2][4], alo[2][4];
        #pragma unroll
        for (int s = 0; s < 2; s++) {
            int mat = ln >> 3;
            uint32_t row  = wid * 64 + t * 16 + (mat & 1) * 8 + (ln & 7);
            uint32_t byteh = s * 32 + (mat >> 1) * 16;
            ldsm_x4(ahi[s][0], ahi[s][1], ahi[s][2], ahi[s][3],
                    sb + SW128(row * 128 + byteh));
            ldsm_x4(alo[s][0], alo[s][1], alo[s][2], alo[s][3],
                    sb + SW128(row * 128 + 64 + byteh));
        }
        float wsrc = (t < 2) ? wtA : wtB;
        int tq = (t & 1) * 16;
        float wt0 = __shfl_sync(0xffffffffu, wsrc, tq + (ln >> 2));
        float wt1 = __shfl_sync(0xffffffffu, wsrc, tq + 8 + (ln >> 2));

        float D2[4] = {0.f, 0.f, 0.f, 0.f};
        #pragma unroll
        for (int s2 = 0; s2 < 4; s2++) {     // gemm2 kstep == gemm1 ntile pair
            unsigned a2hi[4], a2lo[4];
            #pragma unroll
            for (int e = 0; e < 2; e++) {
                int nt = 2 * s2 + e;
                float D1[4] = {0.f, 0.f, 0.f, 0.f};
                mma_bf16(D1, ahi[0], &b1f[nt * 8 + 0]);   // hi*hi  (term0,s0)
                mma_bf16(D1, ahi[1], &b1f[nt * 8 + 2]);   //        (term0,s1)
                mma_bf16(D1, ahi[0], &b1f[nt * 8 + 4]);   // hi*lo  (term1,s0)
                mma_bf16(D1, ahi[1], &b1f[nt * 8 + 6]);   //        (term1,s1)
                mma_bf16(D1, alo[0], &b1f[nt * 8 + 0]);   // lo*hi  (term0,s0)
                mma_bf16(D1, alo[1], &b1f[nt * 8 + 2]);   //        (term0,s1)
                float h0 = fmaxf(D1[0], 0.f) * wt0;
                float h1 = fmaxf(D1[1], 0.f) * wt0;
                float h2 = fmaxf(D1[2], 0.f) * wt1;
                float h3 = fmaxf(D1[3], 0.f) * wt1;
                unsigned p01 = cvt_pack_bf(h0, h1);
                unsigned p23 = cvt_pack_bf(h2, h3);
                a2hi[2 * e + 0] = p01;
                a2hi[2 * e + 1] = p23;
                a2lo[2 * e + 0] = cvt_pack_bf(h0 - bflo_f(p01), h1 - bfhi_f(p01));
                a2lo[2 * e + 1] = cvt_pack_bf(h2 - bflo_f(p23), h3 - bfhi_f(p23));
            }
            // w2 fragments for this kstep: direct from global (fragment order)
            unsigned b2h[2], b2l[2];
            b2h[0] = __ldg(&g_f2[(s2 * 4 + 0) * 32 + ln]);
            b2h[1] = __ldg(&g_f2[(s2 * 4 + 1) * 32 + ln]);
            b2l[0] = __ldg(&g_f2[(s2 * 4 + 2) * 32 + ln]);
            b2l[1] = __ldg(&g_f2[(s2 * 4 + 3) * 32 + ln]);
            mma_bf16(D2, a2hi, b2h);
            mma_bf16(D2, a2hi, b2l);
            mma_bf16(D2, a2lo, b2h);
        }

        // reduce the 8 corner-rows (quads hold distinct rows; cols preserved)
        #pragma unroll
        for (int k = 0; k < 4; k++) {
            D2[k] += __shfl_xor_sync(0xffffffffu, D2[k], 4);
            D2[k] += __shfl_xor_sync(0xffffffffu, D2[k], 8);
            D2[k] += __shfl_xor_sync(0xffffffffu, D2[k], 16);
        }
        int obase = (t < 2) ? (baseAI + 16 * t) : (baseAI + half + 16 * (t - 2));
        if (ln < 4) {
            *reinterpret_cast<float2*>(out + obase + 2 * ln) = make_float2(D2[0], D2[1]);
        } else if (ln < 8) {
            *reinterpret_cast<float2*>(out + obase + 8 + 2 * (ln - 4)) = make_float2(D2[2], D2[3]);
        }
    }
}

extern "C" void kernel_launch(void* const* d_in, const int* in_sizes, int n_in,
                              void* d_out, int out_size)
{
    const float* xyz   = (const float*)d_in[0];
    const float* bound = (const float*)d_in[1];
    const float* table = (const float*)d_in[2];
    const float* w1    = (const float*)d_in[3];
    const float* w2    = (const float*)d_in[4];
    float* out = (float*)d_out;

    int N = in_sizes[0] / 3;

    prep_weights_kernel<<<10, 256>>>(w1, w2);

    // torch-ngp level construction (exact numpy double math)
    LevelParams lev;
    double scale = exp2(log2(513.0 / 16.0) / 15.0);
    long long off = 0;
    for (int i = 0; i < NLEV; i++) {
        int res = (int)ceil(16.0 * pow(scale, (double)i));
        long long cube = (long long)(res + 1) * (res + 1) * (res + 1);
        long long n = cube;
        if (n > (1LL << 19)) n = (1LL << 19);
        n = ((n + 7) / 8) * 8;
        lev.R[i] = res;
        lev.H[i] = (unsigned)n;
        lev.O[i] = (int)off;
        lev.linear[i] = (cube <= n) ? 1 : 0;
        off += n;
    }

    int half = (N * 8) / 2;
    int blocks = (half + 127) / 128;
    grid_fused_kernel<<<blocks, 128>>>(xyz, bound, table, out, lev, N);
}